// round 5
// baseline (speedup 1.0000x reference)
#include <cuda_runtime.h>
#include <cuda_bf16.h>
#include <cstddef>
#include <cstdint>

// ---------------------------------------------------------------------------
// GCN_ValueNet: 3-layer GCN (128->128->64->1) + final dot with W4.
//   u = dinv .* (X@W)   (fused in GEMM epilogue)
//   bucket-CSR by dst (capacity 64/node), built in ONE pass
//   act = tanh((gather + u_self) * dinv + b)   fused in gather epilogue
//   layer-2 gather also fuses the W3 matvec (h2 never materialized)
// GEMM: BK=16 double-buffered, cp.async B tiles, register-staged transposed A.
// edge_index arrives as int32 (JAX x64 disabled).
// ---------------------------------------------------------------------------

#define MAX_NODES 50016
#define BUCKET_CAP 64

__device__ int   g_cnt[MAX_NODES];
__device__ int   g_col[MAX_NODES * BUCKET_CAP];
__device__ float g_dinv[MAX_NODES];
__device__ float g_bufA[MAX_NODES * 128];
__device__ float g_bufB[MAX_NODES * 128];
__device__ float g_bufC[MAX_NODES * 128];
__device__ float g_partials[256];

__device__ __forceinline__ void cp_async16(uint32_t smem, const void* gptr) {
    asm volatile("cp.async.cg.shared.global [%0], [%1], 16;\n" :: "r"(smem), "l"(gptr));
}
__device__ __forceinline__ void cp_commit() {
    asm volatile("cp.async.commit_group;\n" ::: "memory");
}
__device__ __forceinline__ void cp_wait0() {
    asm volatile("cp.async.wait_group 0;\n" ::: "memory");
}

// ---------------- bucket-CSR build ----------------
__global__ void k_zero_int(int* p, int n) {
    int i = blockIdx.x * blockDim.x + threadIdx.x;
    if (i < n) p[i] = 0;
}

__global__ void k_fillcount(const int* __restrict__ src, const int* __restrict__ dst,
                            int E, int* __restrict__ cnt, int* __restrict__ col) {
    int i = blockIdx.x * blockDim.x + threadIdx.x;
    if (i >= E) return;
    int d = dst[i];
    int slot = atomicAdd(&cnt[d], 1);
    if (slot < BUCKET_CAP) col[d * BUCKET_CAP + slot] = src[i];
}

__global__ void k_dinv(const int* __restrict__ cnt, float* __restrict__ dinv, int n) {
    int i = blockIdx.x * blockDim.x + threadIdx.x;
    if (i < n) dinv[i] = rsqrtf((float)cnt[i] + 1.0f);
}

// ---------------- pipelined GEMM: out[r][c] = (A[r][:128].W[:][c]) * dinv[r]
template <int BN, int TN>
__global__ __launch_bounds__(256) void k_gemm_scale(const float* __restrict__ A,
                                                    const float* __restrict__ W,
                                                    const float* __restrict__ dinv,
                                                    float* __restrict__ out, int M) {
    constexpr int BM = 128, BK = 16, TM = 8, K = 128;
    constexpr int NTX = BN / TN;            // 16
    constexpr int NTY = 256 / NTX;          // 16
    static_assert(NTY * TM == BM, "tile");
    __shared__ float sA[2][BK][BM];         // transposed: sA[s][k][row]
    __shared__ float sB[2][BK][BN];

    const int tid  = threadIdx.x;
    const int row0 = blockIdx.x * BM;
    const int tx   = tid % NTX;
    const int ty   = tid / NTX;

    // A-load mapping: row = tid&127 (conflict-free transposed STS),
    // col4 = (tid>>7) and (tid>>7)+2  (two float4 per thread per tile)
    const int aRow = tid & 127;
    const int aC0  = (tid >> 7) * 4;        // 0 or 4
    const int aC1  = aC0 + 8;               // 8 or 12
    const bool aOk = (row0 + aRow) < M;
    const float* aPtr = A + (size_t)(row0 + aRow) * K;

    // B cp.async mapping
    constexpr int F4 = BN / 4;              // float4 per B row
    const int bK = tid / F4;                // BN=128: 0..7 (x2 passes), BN=64: 0..15
    const int bC = (tid % F4) * 4;
    constexpr int BPASS = (BK * F4) / 256;  // 2 for BN=128, 1 for BN=64

    float acc[TM][TN];
#pragma unroll
    for (int i = 0; i < TM; i++)
#pragma unroll
        for (int j = 0; j < TN; j++) acc[i][j] = 0.0f;

    float4 av0, av1;

    // ---- prologue: fill stage 0 ----
    av0 = make_float4(0.f, 0.f, 0.f, 0.f);
    av1 = av0;
    if (aOk) {
        av0 = *(const float4*)(aPtr + aC0);
        av1 = *(const float4*)(aPtr + aC1);
    }
    sA[0][aC0 + 0][aRow] = av0.x; sA[0][aC0 + 1][aRow] = av0.y;
    sA[0][aC0 + 2][aRow] = av0.z; sA[0][aC0 + 3][aRow] = av0.w;
    sA[0][aC1 + 0][aRow] = av1.x; sA[0][aC1 + 1][aRow] = av1.y;
    sA[0][aC1 + 2][aRow] = av1.z; sA[0][aC1 + 3][aRow] = av1.w;
#pragma unroll
    for (int p = 0; p < BPASS; p++) {
        int kk = bK + p * (256 / F4);
        cp_async16((uint32_t)__cvta_generic_to_shared(&sB[0][kk][bC]),
                   W + (size_t)kk * BN + bC);
    }
    cp_commit();
    cp_wait0();
    __syncthreads();

    int buf = 0;
#pragma unroll
    for (int it = 0; it < K / BK; it++) {
        const bool more = (it < K / BK - 1);
        if (more) {
            const int k0 = (it + 1) * BK;
            av0 = make_float4(0.f, 0.f, 0.f, 0.f);
            av1 = av0;
            if (aOk) {
                av0 = *(const float4*)(aPtr + k0 + aC0);
                av1 = *(const float4*)(aPtr + k0 + aC1);
            }
#pragma unroll
            for (int p = 0; p < BPASS; p++) {
                int kk = bK + p * (256 / F4);
                cp_async16((uint32_t)__cvta_generic_to_shared(&sB[buf ^ 1][kk][bC]),
                           W + (size_t)(k0 + kk) * BN + bC);
            }
            cp_commit();
        }

#pragma unroll
        for (int k = 0; k < BK; k++) {
            float a[TM], b[TN];
            float4 a0 = *(const float4*)&sA[buf][k][ty * TM];
            float4 a1 = *(const float4*)&sA[buf][k][ty * TM + 4];
            a[0]=a0.x; a[1]=a0.y; a[2]=a0.z; a[3]=a0.w;
            a[4]=a1.x; a[5]=a1.y; a[6]=a1.z; a[7]=a1.w;
            float4 b0 = *(const float4*)&sB[buf][k][tx * TN];
            b[0]=b0.x; b[1]=b0.y; b[2]=b0.z; b[3]=b0.w;
            if (TN == 8) {
                float4 b1 = *(const float4*)&sB[buf][k][tx * TN + 4];
                b[4]=b1.x; b[5]=b1.y; b[6]=b1.z; b[7]=b1.w;
            }
#pragma unroll
            for (int i = 0; i < TM; i++)
#pragma unroll
                for (int j = 0; j < TN; j++) acc[i][j] += a[i] * b[j];
        }

        if (more) {
            sA[buf ^ 1][aC0 + 0][aRow] = av0.x; sA[buf ^ 1][aC0 + 1][aRow] = av0.y;
            sA[buf ^ 1][aC0 + 2][aRow] = av0.z; sA[buf ^ 1][aC0 + 3][aRow] = av0.w;
            sA[buf ^ 1][aC1 + 0][aRow] = av1.x; sA[buf ^ 1][aC1 + 1][aRow] = av1.y;
            sA[buf ^ 1][aC1 + 2][aRow] = av1.z; sA[buf ^ 1][aC1 + 3][aRow] = av1.w;
            cp_wait0();
        }
        __syncthreads();
        buf ^= 1;
    }

#pragma unroll
    for (int i = 0; i < TM; i++) {
        int r = row0 + ty * TM + i;
        if (r < M) {
            float s = dinv[r];
#pragma unroll
            for (int j = 0; j < TN; j += 4) {
                float4 v;
                v.x = acc[i][j + 0] * s; v.y = acc[i][j + 1] * s;
                v.z = acc[i][j + 2] * s; v.w = acc[i][j + 3] * s;
                *(float4*)(out + (size_t)r * BN + tx * TN + j) = v;
            }
        }
    }
}

// ------- layer-1 gather + fused activation (C=128) -------------------------
__global__ void k_gather_act128(const float* __restrict__ u, const int* __restrict__ col,
                                const int* __restrict__ cnt,
                                const float* __restrict__ dinv, const float* __restrict__ bias,
                                float* __restrict__ out, int N) {
    int warp = (blockIdx.x * blockDim.x + threadIdx.x) >> 5;
    int lane = threadIdx.x & 31;
    if (warp >= N) return;
    const int* bucket = col + (size_t)warp * BUCKET_CAP;
    int m = cnt[warp];

    float4 acc = make_float4(0.f, 0.f, 0.f, 0.f);
    int e = 0;
    for (; e + 4 <= m; e += 4) {
        int s0 = __ldg(&bucket[e + 0]);
        int s1 = __ldg(&bucket[e + 1]);
        int s2 = __ldg(&bucket[e + 2]);
        int s3 = __ldg(&bucket[e + 3]);
        float4 v0 = *((const float4*)(u + (size_t)s0 * 128) + lane);
        float4 v1 = *((const float4*)(u + (size_t)s1 * 128) + lane);
        float4 v2 = *((const float4*)(u + (size_t)s2 * 128) + lane);
        float4 v3 = *((const float4*)(u + (size_t)s3 * 128) + lane);
        acc.x += v0.x + v1.x + v2.x + v3.x;
        acc.y += v0.y + v1.y + v2.y + v3.y;
        acc.z += v0.z + v1.z + v2.z + v3.z;
        acc.w += v0.w + v1.w + v2.w + v3.w;
    }
    for (; e < m; e++) {
        int s = __ldg(&bucket[e]);
        float4 v = *((const float4*)(u + (size_t)s * 128) + lane);
        acc.x += v.x; acc.y += v.y; acc.z += v.z; acc.w += v.w;
    }
    float4 self = *((const float4*)(u + (size_t)warp * 128) + lane);
    float  dv = dinv[warp];
    float4 bb = *((const float4*)bias + lane);
    float4 r;
    r.x = tanhf((acc.x + self.x) * dv + bb.x);
    r.y = tanhf((acc.y + self.y) * dv + bb.y);
    r.z = tanhf((acc.z + self.z) * dv + bb.z);
    r.w = tanhf((acc.w + self.w) * dv + bb.w);
    *((float4*)(out + (size_t)warp * 128) + lane) = r;
}

// ------- layer-2 gather + activation + FUSED W3 matvec (C=64) --------------
__global__ void k_gather_act64_mv(const float* __restrict__ u, const int* __restrict__ col,
                                  const int* __restrict__ cnt,
                                  const float* __restrict__ dinv, const float* __restrict__ bias,
                                  const float* __restrict__ W3,
                                  float* __restrict__ u3, int N) {
    int warp = (blockIdx.x * blockDim.x + threadIdx.x) >> 5;
    int lane = threadIdx.x & 31;
    if (warp >= N) return;
    const int* bucket = col + (size_t)warp * BUCKET_CAP;
    int m = cnt[warp];

    float2 acc = make_float2(0.f, 0.f);
    int e = 0;
    for (; e + 4 <= m; e += 4) {
        int s0 = __ldg(&bucket[e + 0]);
        int s1 = __ldg(&bucket[e + 1]);
        int s2 = __ldg(&bucket[e + 2]);
        int s3 = __ldg(&bucket[e + 3]);
        float2 v0 = *((const float2*)(u + (size_t)s0 * 64) + lane);
        float2 v1 = *((const float2*)(u + (size_t)s1 * 64) + lane);
        float2 v2 = *((const float2*)(u + (size_t)s2 * 64) + lane);
        float2 v3 = *((const float2*)(u + (size_t)s3 * 64) + lane);
        acc.x += v0.x + v1.x + v2.x + v3.x;
        acc.y += v0.y + v1.y + v2.y + v3.y;
    }
    for (; e < m; e++) {
        int s = __ldg(&bucket[e]);
        float2 v = *((const float2*)(u + (size_t)s * 64) + lane);
        acc.x += v.x; acc.y += v.y;
    }
    float2 self = *((const float2*)(u + (size_t)warp * 64) + lane);
    float  dv = dinv[warp];
    float2 bb = *((const float2*)bias + lane);
    float hx = tanhf((acc.x + self.x) * dv + bb.x);
    float hy = tanhf((acc.y + self.y) * dv + bb.y);
    float2 w = *((const float2*)W3 + lane);
    float s = hx * w.x + hy * w.y;
#pragma unroll
    for (int o = 16; o; o >>= 1) s += __shfl_xor_sync(0xFFFFFFFFu, s, o);
    if (lane == 0) u3[warp] = s * dv;
}

// ------- layer3 gather + activation + dot with W4 --------------------------
__global__ void k_gather3_dot(const float* __restrict__ u3, const int* __restrict__ col,
                              const int* __restrict__ cnt,
                              const float* __restrict__ dinv, const float* __restrict__ b3,
                              const float* __restrict__ W4, float* __restrict__ partials,
                              int N) {
    __shared__ float sm[256];
    int i = blockIdx.x * 256 + threadIdx.x;
    float contrib = 0.0f;
    if (i < N) {
        const int* bucket = col + (size_t)i * BUCKET_CAP;
        int m = cnt[i];
        float acc = 0.0f;
        for (int e = 0; e < m; e++) acc += u3[__ldg(&bucket[e])];
        float v = tanhf((acc + u3[i]) * dinv[i] + b3[0]);
        contrib = W4[i] * v;
    }
    sm[threadIdx.x] = contrib;
    __syncthreads();
    for (int s = 128; s; s >>= 1) {
        if (threadIdx.x < s) sm[threadIdx.x] += sm[threadIdx.x + s];
        __syncthreads();
    }
    if (threadIdx.x == 0) partials[blockIdx.x] = sm[0];
}

__global__ void k_final_reduce(const float* __restrict__ partials,
                               const float* __restrict__ b4,
                               float* __restrict__ out, int nb) {
    __shared__ float sm[256];
    sm[threadIdx.x] = (threadIdx.x < nb) ? partials[threadIdx.x] : 0.0f;
    __syncthreads();
    for (int s = 128; s; s >>= 1) {
        if (threadIdx.x < s) sm[threadIdx.x] += sm[threadIdx.x + s];
        __syncthreads();
    }
    if (threadIdx.x == 0) out[0] = sm[0] + b4[0];
}

// ---------------------------------------------------------------------------
extern "C" void kernel_launch(void* const* d_in, const int* in_sizes, int n_in,
                              void* d_out, int out_size) {
    const float* x   = (const float*)d_in[0];
    const int*   ei  = (const int*)d_in[1];
    const float* W1  = (const float*)d_in[2];
    const float* b1  = (const float*)d_in[3];
    const float* W2  = (const float*)d_in[4];
    const float* b2  = (const float*)d_in[5];
    const float* W3  = (const float*)d_in[6];
    const float* b3  = (const float*)d_in[7];
    const float* W4  = (const float*)d_in[8];
    const float* b4  = (const float*)d_in[9];

    int N = in_sizes[0] / 128;
    int E = in_sizes[1] / 2;
    const int* src = ei;
    const int* dst = ei + E;

    int *cnt, *col;
    float *dinv, *bufA, *bufB, *bufC, *partials;
    cudaGetSymbolAddress((void**)&cnt, g_cnt);
    cudaGetSymbolAddress((void**)&col, g_col);
    cudaGetSymbolAddress((void**)&dinv, g_dinv);
    cudaGetSymbolAddress((void**)&bufA, g_bufA);
    cudaGetSymbolAddress((void**)&bufB, g_bufB);
    cudaGetSymbolAddress((void**)&bufC, g_bufC);
    cudaGetSymbolAddress((void**)&partials, g_partials);

    const int nBlkN = (N + 255) / 256;   // 196

    // ---- bucket-CSR build + dinv ----
    k_zero_int<<<nBlkN, 256>>>(cnt, N);
    k_fillcount<<<(E + 255) / 256, 256>>>(src, dst, E, cnt, col);
    k_dinv<<<nBlkN, 256>>>(cnt, dinv, N);

    // ---- layer 1 (128 -> 128) ----
    k_gemm_scale<128, 8><<<(N + 127) / 128, 256>>>(x, W1, dinv, bufA, N);   // u1
    k_gather_act128<<<(N * 32 + 255) / 256, 256>>>(bufA, col, cnt, dinv, b1, bufB, N);  // h1

    // ---- layer 2 (128 -> 64) + fused layer-3 matvec ----
    k_gemm_scale<64, 4><<<(N + 127) / 128, 256>>>(bufB, W2, dinv, bufC, N); // u2
    k_gather_act64_mv<<<(N * 32 + 255) / 256, 256>>>(bufC, col, cnt, dinv, b2, W3, bufA, N); // u3

    // ---- layer 3 aggregation + final dot ----
    k_gather3_dot<<<nBlkN, 256>>>(bufA, col, cnt, dinv, b3, W4, partials, N);
    k_final_reduce<<<1, 256>>>(partials, b4, (float*)d_out, nBlkN);
}

// round 7
// speedup vs baseline: 1.3966x; 1.3966x over previous
#include <cuda_runtime.h>
#include <cuda_bf16.h>
#include <cstddef>
#include <cstdint>

// ---------------------------------------------------------------------------
// GCN_ValueNet: 3-layer GCN (128->128->64->1) + final dot with W4.
//   u = dinv .* (X@W)   via SPLIT-tf32 mma.sync GEMM (fp32-class accuracy):
//       x = hi + lo (each tf32);  D += ah*bh + al*bh + ah*bl
//   bucket-CSR by dst (capacity 64/node), built in ONE pass
//   act = tanh((gather + u_self) * dinv + b)   fused in gather epilogue
//   layer-2 gather also fuses the W3 matvec (h2 never materialized)
// edge_index arrives as int32 (JAX x64 disabled).
// ---------------------------------------------------------------------------

#define MAX_NODES 50016
#define BUCKET_CAP 64

__device__ int   g_cnt[MAX_NODES];
__device__ int   g_col[MAX_NODES * BUCKET_CAP];
__device__ float g_dinv[MAX_NODES];
__device__ float g_bufA[MAX_NODES * 128];
__device__ float g_bufB[MAX_NODES * 128];
__device__ float g_bufC[MAX_NODES * 128];
__device__ float g_partials[256];

__device__ __forceinline__ uint32_t f2tf32(float f) {
    uint32_t r;
    asm("cvt.rna.tf32.f32 %0, %1;" : "=r"(r) : "f"(f));
    return r;
}

__device__ __forceinline__ void split_tf32(float x, uint32_t& hi, uint32_t& lo) {
    uint32_t h = f2tf32(x);
    float hf = __uint_as_float(h);       // tf32 value is exactly representable in fp32
    hi = h;
    lo = f2tf32(x - hf);
}

__device__ __forceinline__ void mma_tf32(float* d, const uint32_t* a,
                                         const uint32_t* b, const float* c) {
    asm("mma.sync.aligned.m16n8k8.row.col.f32.tf32.tf32.f32 "
        "{%0,%1,%2,%3},{%4,%5,%6,%7},{%8,%9},{%10,%11,%12,%13};"
        : "=f"(d[0]), "=f"(d[1]), "=f"(d[2]), "=f"(d[3])
        : "r"(a[0]), "r"(a[1]), "r"(a[2]), "r"(a[3]),
          "r"(b[0]), "r"(b[1]),
          "f"(c[0]), "f"(c[1]), "f"(c[2]), "f"(c[3]));
}

// ---------------- bucket-CSR build ----------------
__global__ void k_zero_int(int* p, int n) {
    int i = blockIdx.x * blockDim.x + threadIdx.x;
    if (i < n) p[i] = 0;
}

__global__ void k_fillcount(const int* __restrict__ src, const int* __restrict__ dst,
                            int E, int* __restrict__ cnt, int* __restrict__ col) {
    int i = blockIdx.x * blockDim.x + threadIdx.x;
    if (i >= E) return;
    int d = dst[i];
    int slot = atomicAdd(&cnt[d], 1);
    if (slot < BUCKET_CAP) col[d * BUCKET_CAP + slot] = src[i];
}

__global__ void k_dinv(const int* __restrict__ cnt, float* __restrict__ dinv, int n) {
    int i = blockIdx.x * blockDim.x + threadIdx.x;
    if (i < n) dinv[i] = rsqrtf((float)cnt[i] + 1.0f);
}

// ------- split-tf32 GEMM: out[r][c] = (A[r][:128].W[:][c]) * dinv[r] --------
// BM=128, BK=16, 256 threads = 8 warps as 4(M) x 2(N).
// Warp tile: 32(M) x BN/2(N) -> 2 mtiles (m16) x NT ntiles (n8), k8 steps.
template <int BN>
__global__ __launch_bounds__(256) void k_gemm_tf32(const float* __restrict__ A,
                                                   const float* __restrict__ W,
                                                   const float* __restrict__ dinv,
                                                   float* __restrict__ out, int M) {
    constexpr int BM = 128, BK = 16, K = 128;
    constexpr int SAS = 20;        // 20*lq + lr distinct mod 32 -> conflict-free
    constexpr int SBS = BN + 8;    // SBS % 32 == 8 -> banks 8*lr+lq all distinct
    constexpr int NT  = BN / 16;   // n8 tiles per warp (8 for BN=128, 4 for BN=64)
    __shared__ uint32_t sAh[BM][SAS], sAl[BM][SAS];
    __shared__ uint32_t sBh[BK][SBS], sBl[BK][SBS];

    const int tid    = threadIdx.x;
    const int wid    = tid >> 5;
    const int lane   = tid & 31;
    const int warp_m = wid & 3;
    const int warp_n = wid >> 2;
    const int row0   = blockIdx.x * BM;

    float acc[2][NT][4];
#pragma unroll
    for (int m = 0; m < 2; m++)
#pragma unroll
        for (int n = 0; n < NT; n++)
#pragma unroll
            for (int q = 0; q < 4; q++) acc[m][n][q] = 0.0f;

    // A global->smem: 2 passes of 64 rows, one float4 along k per thread
    const int aRow = tid >> 2;            // 0..63
    const int aCol = (tid & 3) * 4;       // 0,4,8,12
    // B global->smem
    constexpr int BF4   = BN / 4;
    constexpr int BROWS = 256 / BF4;      // 8 (BN=128) or 16 (BN=64)
    const int bRow = tid / BF4;
    const int bCol = (tid % BF4) * 4;

    const int lq = lane >> 2;             // 0..7
    const int lr = lane & 3;              // 0..3

#pragma unroll
    for (int kt = 0; kt < K / BK; kt++) {
        const int k0 = kt * BK;
#pragma unroll
        for (int p = 0; p < 2; p++) {
            int r = aRow + p * 64;
            float4 v = make_float4(0.f, 0.f, 0.f, 0.f);
            if (row0 + r < M)
                v = *(const float4*)(A + (size_t)(row0 + r) * K + k0 + aCol);
            split_tf32(v.x, sAh[r][aCol + 0], sAl[r][aCol + 0]);
            split_tf32(v.y, sAh[r][aCol + 1], sAl[r][aCol + 1]);
            split_tf32(v.z, sAh[r][aCol + 2], sAl[r][aCol + 2]);
            split_tf32(v.w, sAh[r][aCol + 3], sAl[r][aCol + 3]);
        }
#pragma unroll
        for (int p = 0; p < BK / BROWS; p++) {
            int kk = bRow + p * BROWS;
            float4 v = *(const float4*)(W + (size_t)(k0 + kk) * BN + bCol);
            split_tf32(v.x, sBh[kk][bCol + 0], sBl[kk][bCol + 0]);
            split_tf32(v.y, sBh[kk][bCol + 1], sBl[kk][bCol + 1]);
            split_tf32(v.z, sBh[kk][bCol + 2], sBl[kk][bCol + 2]);
            split_tf32(v.w, sBh[kk][bCol + 3], sBl[kk][bCol + 3]);
        }
        __syncthreads();

#pragma unroll
        for (int k8 = 0; k8 < BK / 8; k8++) {
            const int kb = k8 * 8;
            uint32_t ah[2][4], al[2][4];
#pragma unroll
            for (int m = 0; m < 2; m++) {
                int r = warp_m * 32 + m * 16 + lq;
                ah[m][0] = sAh[r    ][kb + lr    ];
                ah[m][1] = sAh[r + 8][kb + lr    ];
                ah[m][2] = sAh[r    ][kb + lr + 4];
                ah[m][3] = sAh[r + 8][kb + lr + 4];
                al[m][0] = sAl[r    ][kb + lr    ];
                al[m][1] = sAl[r + 8][kb + lr    ];
                al[m][2] = sAl[r    ][kb + lr + 4];
                al[m][3] = sAl[r + 8][kb + lr + 4];
            }
#pragma unroll
            for (int n = 0; n < NT; n++) {
                int c = warp_n * (BN / 2) + n * 8 + lq;
                uint32_t bh[2], bl[2];
                bh[0] = sBh[kb + lr    ][c];
                bh[1] = sBh[kb + lr + 4][c];
                bl[0] = sBl[kb + lr    ][c];
                bl[1] = sBl[kb + lr + 4][c];
#pragma unroll
                for (int m = 0; m < 2; m++) {
                    mma_tf32(acc[m][n], ah[m], bh, acc[m][n]);
                    mma_tf32(acc[m][n], al[m], bh, acc[m][n]);
                    mma_tf32(acc[m][n], ah[m], bl, acc[m][n]);
                }
            }
        }
        __syncthreads();
    }

    // epilogue: scale rows by dinv, store float2 pairs
#pragma unroll
    for (int m = 0; m < 2; m++) {
        int r0 = row0 + warp_m * 32 + m * 16 + lq;
        int r1 = r0 + 8;
        float d0 = (r0 < M) ? dinv[r0] : 0.0f;
        float d1 = (r1 < M) ? dinv[r1] : 0.0f;
#pragma unroll
        for (int n = 0; n < NT; n++) {
            int c = warp_n * (BN / 2) + n * 8 + lr * 2;
            if (r0 < M) {
                float2 v; v.x = acc[m][n][0] * d0; v.y = acc[m][n][1] * d0;
                *(float2*)(out + (size_t)r0 * BN + c) = v;
            }
            if (r1 < M) {
                float2 v; v.x = acc[m][n][2] * d1; v.y = acc[m][n][3] * d1;
                *(float2*)(out + (size_t)r1 * BN + c) = v;
            }
        }
    }
}

// ------- layer-1 gather + fused activation (C=128) -------------------------
__global__ void k_gather_act128(const float* __restrict__ u, const int* __restrict__ col,
                                const int* __restrict__ cnt,
                                const float* __restrict__ dinv, const float* __restrict__ bias,
                                float* __restrict__ out, int N) {
    int warp = (blockIdx.x * blockDim.x + threadIdx.x) >> 5;
    int lane = threadIdx.x & 31;
    if (warp >= N) return;
    const int* bucket = col + (size_t)warp * BUCKET_CAP;
    int m = cnt[warp];

    float4 acc = make_float4(0.f, 0.f, 0.f, 0.f);
    int e = 0;
    for (; e + 4 <= m; e += 4) {
        int s0 = __ldg(&bucket[e + 0]);
        int s1 = __ldg(&bucket[e + 1]);
        int s2 = __ldg(&bucket[e + 2]);
        int s3 = __ldg(&bucket[e + 3]);
        float4 v0 = *((const float4*)(u + (size_t)s0 * 128) + lane);
        float4 v1 = *((const float4*)(u + (size_t)s1 * 128) + lane);
        float4 v2 = *((const float4*)(u + (size_t)s2 * 128) + lane);
        float4 v3 = *((const float4*)(u + (size_t)s3 * 128) + lane);
        acc.x += v0.x + v1.x + v2.x + v3.x;
        acc.y += v0.y + v1.y + v2.y + v3.y;
        acc.z += v0.z + v1.z + v2.z + v3.z;
        acc.w += v0.w + v1.w + v2.w + v3.w;
    }
    for (; e < m; e++) {
        int s = __ldg(&bucket[e]);
        float4 v = *((const float4*)(u + (size_t)s * 128) + lane);
        acc.x += v.x; acc.y += v.y; acc.z += v.z; acc.w += v.w;
    }
    float4 self = *((const float4*)(u + (size_t)warp * 128) + lane);
    float  dv = dinv[warp];
    float4 bb = *((const float4*)bias + lane);
    float4 r;
    r.x = tanhf((acc.x + self.x) * dv + bb.x);
    r.y = tanhf((acc.y + self.y) * dv + bb.y);
    r.z = tanhf((acc.z + self.z) * dv + bb.z);
    r.w = tanhf((acc.w + self.w) * dv + bb.w);
    *((float4*)(out + (size_t)warp * 128) + lane) = r;
}

// ------- layer-2 gather + activation + FUSED W3 matvec (C=64) --------------
__global__ void k_gather_act64_mv(const float* __restrict__ u, const int* __restrict__ col,
                                  const int* __restrict__ cnt,
                                  const float* __restrict__ dinv, const float* __restrict__ bias,
                                  const float* __restrict__ W3,
                                  float* __restrict__ u3, int N) {
    int warp = (blockIdx.x * blockDim.x + threadIdx.x) >> 5;
    int lane = threadIdx.x & 31;
    if (warp >= N) return;
    const int* bucket = col + (size_t)warp * BUCKET_CAP;
    int m = cnt[warp];

    float2 acc = make_float2(0.f, 0.f);
    int e = 0;
    for (; e + 4 <= m; e += 4) {
        int s0 = __ldg(&bucket[e + 0]);
        int s1 = __ldg(&bucket[e + 1]);
        int s2 = __ldg(&bucket[e + 2]);
        int s3 = __ldg(&bucket[e + 3]);
        float2 v0 = *((const float2*)(u + (size_t)s0 * 64) + lane);
        float2 v1 = *((const float2*)(u + (size_t)s1 * 64) + lane);
        float2 v2 = *((const float2*)(u + (size_t)s2 * 64) + lane);
        float2 v3 = *((const float2*)(u + (size_t)s3 * 64) + lane);
        acc.x += v0.x + v1.x + v2.x + v3.x;
        acc.y += v0.y + v1.y + v2.y + v3.y;
    }
    for (; e < m; e++) {
        int s = __ldg(&bucket[e]);
        float2 v = *((const float2*)(u + (size_t)s * 64) + lane);
        acc.x += v.x; acc.y += v.y;
    }
    float2 self = *((const float2*)(u + (size_t)warp * 64) + lane);
    float  dv = dinv[warp];
    float2 bb = *((const float2*)bias + lane);
    float hx = tanhf((acc.x + self.x) * dv + bb.x);
    float hy = tanhf((acc.y + self.y) * dv + bb.y);
    float2 w = *((const float2*)W3 + lane);
    float s = hx * w.x + hy * w.y;
#pragma unroll
    for (int o = 16; o; o >>= 1) s += __shfl_xor_sync(0xFFFFFFFFu, s, o);
    if (lane == 0) u3[warp] = s * dv;
}

// ------- layer3 gather + activation + dot with W4 --------------------------
__global__ void k_gather3_dot(const float* __restrict__ u3, const int* __restrict__ col,
                              const int* __restrict__ cnt,
                              const float* __restrict__ dinv, const float* __restrict__ b3,
                              const float* __restrict__ W4, float* __restrict__ partials,
                              int N) {
    __shared__ float sm[256];
    int i = blockIdx.x * 256 + threadIdx.x;
    float contrib = 0.0f;
    if (i < N) {
        const int* bucket = col + (size_t)i * BUCKET_CAP;
        int m = cnt[i];
        float acc = 0.0f;
        for (int e = 0; e < m; e++) acc += u3[__ldg(&bucket[e])];
        float v = tanhf((acc + u3[i]) * dinv[i] + b3[0]);
        contrib = W4[i] * v;
    }
    sm[threadIdx.x] = contrib;
    __syncthreads();
    for (int s = 128; s; s >>= 1) {
        if (threadIdx.x < s) sm[threadIdx.x] += sm[threadIdx.x + s];
        __syncthreads();
    }
    if (threadIdx.x == 0) partials[blockIdx.x] = sm[0];
}

__global__ void k_final_reduce(const float* __restrict__ partials,
                               const float* __restrict__ b4,
                               float* __restrict__ out, int nb) {
    __shared__ float sm[256];
    sm[threadIdx.x] = (threadIdx.x < nb) ? partials[threadIdx.x] : 0.0f;
    __syncthreads();
    for (int s = 128; s; s >>= 1) {
        if (threadIdx.x < s) sm[threadIdx.x] += sm[threadIdx.x + s];
        __syncthreads();
    }
    if (threadIdx.x == 0) out[0] = sm[0] + b4[0];
}

// ---------------------------------------------------------------------------
extern "C" void kernel_launch(void* const* d_in, const int* in_sizes, int n_in,
                              void* d_out, int out_size) {
    const float* x   = (const float*)d_in[0];
    const int*   ei  = (const int*)d_in[1];
    const float* W1  = (const float*)d_in[2];
    const float* b1  = (const float*)d_in[3];
    const float* W2  = (const float*)d_in[4];
    const float* b2  = (const float*)d_in[5];
    const float* W3  = (const float*)d_in[6];
    const float* b3  = (const float*)d_in[7];
    const float* W4  = (const float*)d_in[8];
    const float* b4  = (const float*)d_in[9];

    int N = in_sizes[0] / 128;
    int E = in_sizes[1] / 2;
    const int* src = ei;
    const int* dst = ei + E;

    int *cnt, *col;
    float *dinv, *bufA, *bufB, *bufC, *partials;
    cudaGetSymbolAddress((void**)&cnt, g_cnt);
    cudaGetSymbolAddress((void**)&col, g_col);
    cudaGetSymbolAddress((void**)&dinv, g_dinv);
    cudaGetSymbolAddress((void**)&bufA, g_bufA);
    cudaGetSymbolAddress((void**)&bufB, g_bufB);
    cudaGetSymbolAddress((void**)&bufC, g_bufC);
    cudaGetSymbolAddress((void**)&partials, g_partials);

    const int nBlkN = (N + 255) / 256;

    // ---- bucket-CSR build + dinv ----
    k_zero_int<<<nBlkN, 256>>>(cnt, N);
    k_fillcount<<<(E + 255) / 256, 256>>>(src, dst, E, cnt, col);
    k_dinv<<<nBlkN, 256>>>(cnt, dinv, N);

    // ---- layer 1 (128 -> 128) ----
    k_gemm_tf32<128><<<(N + 127) / 128, 256>>>(x, W1, dinv, bufA, N);       // u1
    k_gather_act128<<<(N * 32 + 255) / 256, 256>>>(bufA, col, cnt, dinv, b1, bufB, N);  // h1

    // ---- layer 2 (128 -> 64) + fused layer-3 matvec ----
    k_gemm_tf32<64><<<(N + 127) / 128, 256>>>(bufB, W2, dinv, bufC, N);     // u2
    k_gather_act64_mv<<<(N * 32 + 255) / 256, 256>>>(bufC, col, cnt, dinv, b2, W3, bufA, N); // u3

    // ---- layer 3 aggregation + final dot ----
    k_gather3_dot<<<nBlkN, 256>>>(bufA, col, cnt, dinv, b3, W4, partials, N);
    k_final_reduce<<<1, 256>>>(partials, b4, (float*)d_out, nBlkN);
}